// round 13
// baseline (speedup 1.0000x reference)
#include <cuda_runtime.h>
#include <cstdint>
#include <cstddef>

// 1x1 conv as GEMM on HMMA, sm_103 target (no tcgen05 in harness toolchain).
// out[b,o,p] = sum_i W[i,o] * x[b,i,p];  B=32, CIN=COUT=128, HW=16384.
// R13: 3-pass bf16 split (w=wh+wl, x=xh+xl; out = wh*xh + wh*xl + wl*xh)
// using mma.m16n8k16.bf16 (2x MACs/instr vs tf32 m16n8k8). Frags are bf16x2
// k-pairs so LDS volume matches the tf32 kernel; MMA instr count x1.5 at
// (hypothesized) 2x rate -> 0.75x tensor cycles. rel_err ~1e-5.
// Staging: LDG.128 -> trunc/residual split -> STS.128 (no cp.async),
// 2 smem buffers, LDG one chunk ahead, ONE barrier per chunk.
// Tile M=128 x N=128 x K=128; 8 warps 2(M)x4(N), warp m64n32. 2 CTAs/SM.

#define HW      16384
#define NCH     128
#define TILE_N  128
#define NTILES  4096
#define GRID    304
#define NTHREADS 256

// word (uint32) offsets in smem
#define A_HI    0                     // 128 o x 72 words (bf16x2 k-pairs, pad 8)
#define A_LO    9216
#define B_OFF   18432                 // 2 buffers x 4096 words (xh 2048 + xl 2048)
#define SMEM_WORDS (18432 + 2 * 4096)
#define SMEM_BYTES (SMEM_WORDS * 4)   // 106496 B

__device__ __forceinline__ uint32_t smem_u32(const void* p) {
    uint32_t a;
    asm("{ .reg .u64 t; cvta.to.shared.u64 t, %1; cvt.u32.u64 %0, t; }" : "=r"(a) : "l"(p));
    return a;
}

__device__ __forceinline__ void mma_bf16(float c[4], const uint32_t a[4],
                                         uint32_t b0, uint32_t b1) {
    asm volatile(
        "mma.sync.aligned.m16n8k16.row.col.f32.bf16.bf16.f32 "
        "{%0,%1,%2,%3},{%4,%5,%6,%7},{%8,%9},{%0,%1,%2,%3};"
        : "+f"(c[0]), "+f"(c[1]), "+f"(c[2]), "+f"(c[3])
        : "r"(a[0]), "r"(a[1]), "r"(a[2]), "r"(a[3]), "r"(b0), "r"(b1));
}

// split two fp32 (rows k, k+1) into hi bf16x2 (trunc) and lo bf16x2 (residual)
__device__ __forceinline__ void split2(float a, float b, uint32_t& h, uint32_t& l) {
    uint32_t ab = __float_as_uint(a), bb = __float_as_uint(b);
    h = __byte_perm(ab, bb, 0x7632);               // lo16=a.hi16, hi16=b.hi16
    float ah = __uint_as_float(ab & 0xFFFF0000u);
    float bh = __uint_as_float(bb & 0xFFFF0000u);
    float la = a - ah, lb = b - bh;                // exact residuals
    asm("cvt.rn.bf16x2.f32 %0, %1, %2;" : "=r"(l) : "f"(lb), "f"(la));
}

__global__ __launch_bounds__(NTHREADS, 2)
void conv1x1_bf16_kernel(const float* __restrict__ x,
                         const float* __restrict__ w,
                         float* __restrict__ out)
{
    extern __shared__ __align__(16) float smemf[];
    uint32_t* smem = (uint32_t*)smemf;
    const int tid = threadIdx.x;
    const int lid = tid & 31;
    const int wid = tid >> 5;
    const int mw  = wid & 1;          // M half
    const int nw  = wid >> 1;         // N quarter
    const int bid = blockIdx.x;
    const int lr  = lid >> 2;         // 0..7
    const int lc  = lid & 3;          // 0..3

    // ---- W split -> A_HI/A_LO smem once. word(o,kp): k16*8 + (kpb&3)*2 + (kpb>>2)
    for (int i = tid; i < 128 * 64; i += NTHREADS) {
        int o = i & 127, kp = i >> 7;             // kp = k/2, 0..63
        float a = __ldg(&w[(2 * kp) * NCH + o]);
        float b = __ldg(&w[(2 * kp + 1) * NCH + o]);
        uint32_t h, l;
        split2(a, b, h, l);
        int wd = o * 72 + (kp >> 3) * 8 + (kp & 3) * 2 + ((kp >> 2) & 1);
        smem[A_HI + wd] = h;
        smem[A_LO + wd] = l;
    }
    __syncthreads();

    const int n     = (NTILES - bid + GRID - 1) / GRID;
    const int total = 4 * n;                      // 32-row chunks

    // loader mapping: px4 = 4 px (contiguous across warp), row-pairs rp, rp+8
    const int px4 = (tid & 31) * 4;
    const int rp  = tid >> 5;                     // 0..7

    float4 v0, v1, v2, v3;                        // held LDG results (1 chunk ahead)
    auto ldg_chunk = [&](int g) {
        int tt = bid + (g >> 2) * GRID;
        int b  = tt >> 7;
        int p0 = (tt & 127) * TILE_N;
        int k0 = (g & 3) * 32;
        const float* xb = x + ((size_t)b * NCH + k0) * HW + p0 + px4;
        const float* r0 = xb + (size_t)(2 * rp) * HW;
        v0 = *(const float4*)(r0);                // row 2rp
        v1 = *(const float4*)(r0 + HW);           // row 2rp+1
        v2 = *(const float4*)(r0 + 16 * HW);      // row 16+2rp
        v3 = *(const float4*)(r0 + 17 * HW);      // row 17+2rp
    };
    auto sts_chunk = [&](int g) {
        uint32_t* buf = smem + B_OFF + (g & 1) * 4096;
        uint4 h, l;
        split2(v0.x, v1.x, h.x, l.x); split2(v0.y, v1.y, h.y, l.y);
        split2(v0.z, v1.z, h.z, l.z); split2(v0.w, v1.w, h.w, l.w);
        int w0 = rp * 128 + (px4 ^ ((rp & 3) << 3));
        *(uint4*)(buf + w0)        = h;           // xh
        *(uint4*)(buf + 2048 + w0) = l;           // xl
        split2(v2.x, v3.x, h.x, l.x); split2(v2.y, v3.y, h.y, l.y);
        split2(v2.z, v3.z, h.z, l.z); split2(v2.w, v3.w, h.w, l.w);
        int rp2 = rp + 8;
        int w1 = rp2 * 128 + (px4 ^ ((rp2 & 3) << 3));
        *(uint4*)(buf + w1)        = h;
        *(uint4*)(buf + 2048 + w1) = l;
    };

    ldg_chunk(0);

    const uint32_t* Asm_hi = smem + A_HI + (mw * 64 + lr) * 72 + lc * 2;
    const uint32_t* Asm_lo = smem + A_LO + (mw * 64 + lr) * 72 + lc * 2;
    float acc[4][4][4];

    #pragma unroll 1
    for (int g = 0; g < total; g++) {
        sts_chunk(g);                             // buf safe: bar(g-1) after compute(g-2)
        if (g + 1 < total) ldg_chunk(g + 1);
        __syncthreads();                          // STS(g) visible; compute(g-1) done

        if ((g & 3) == 0) {
            #pragma unroll
            for (int mt = 0; mt < 4; mt++)
                #pragma unroll
                for (int nt = 0; nt < 4; nt++)
                    #pragma unroll
                    for (int q = 0; q < 4; q++) acc[mt][nt][q] = 0.f;
        }

        const uint32_t* Bb = smem + B_OFF + (g & 1) * 4096 + nw * 32 + lr;

        #pragma unroll
        for (int kb = 0; kb < 2; kb++) {
            const int k16 = (g & 3) * 2 + kb;     // global k16 block 0..7
            uint32_t af[4][4];
            #pragma unroll
            for (int mt = 0; mt < 4; mt++) {      // A hi frags: 2x LDS.64 per mt
                const uint32_t* pa = Asm_hi + mt * 16 * 72 + k16 * 8;
                asm volatile("ld.shared.v2.b32 {%0,%1}, [%2];"
                    : "=r"(af[mt][0]), "=r"(af[mt][2]) : "r"(smem_u32(pa)));
                asm volatile("ld.shared.v2.b32 {%0,%1}, [%2];"
                    : "=r"(af[mt][1]), "=r"(af[mt][3]) : "r"(smem_u32(pa + 8 * 72)));
            }
            uint32_t bh[4][2], bl[4][2];
            const uint32_t* pb0 = Bb + (kb * 8 + lc) * 128;      // b0 row (kpair)
            #pragma unroll
            for (int nt = 0; nt < 4; nt++) {
                int sw = (nt ^ lc) * 8;
                bh[nt][0] = pb0[sw];
                bh[nt][1] = pb0[4 * 128 + sw];                   // b1 row = +4 kpairs
                bl[nt][0] = pb0[2048 + sw];
                bl[nt][1] = pb0[2048 + 4 * 128 + sw];
            }
            #pragma unroll
            for (int mt = 0; mt < 4; mt++)
                #pragma unroll
                for (int nt = 0; nt < 4; nt++) {
                    mma_bf16(acc[mt][nt], af[mt], bh[nt][0], bh[nt][1]);  // wh*xh
                    mma_bf16(acc[mt][nt], af[mt], bl[nt][0], bl[nt][1]);  // wh*xl
                }
            #pragma unroll
            for (int mt = 0; mt < 4; mt++) {      // A lo frags (reuse regs)
                const uint32_t* pa = Asm_lo + mt * 16 * 72 + k16 * 8;
                asm volatile("ld.shared.v2.b32 {%0,%1}, [%2];"
                    : "=r"(af[mt][0]), "=r"(af[mt][2]) : "r"(smem_u32(pa)));
                asm volatile("ld.shared.v2.b32 {%0,%1}, [%2];"
                    : "=r"(af[mt][1]), "=r"(af[mt][3]) : "r"(smem_u32(pa + 8 * 72)));
            }
            #pragma unroll
            for (int mt = 0; mt < 4; mt++)
                #pragma unroll
                for (int nt = 0; nt < 4; nt++)
                    mma_bf16(acc[mt][nt], af[mt], bh[nt][0], bh[nt][1]);  // wl*xh
        }

        if ((g & 3) == 3) {                       // tile finished -> epilogue
            int tt = bid + (g >> 2) * GRID;
            int b  = tt >> 7;
            int p0 = (tt & 127) * TILE_N;
            float* ob = out + (size_t)b * NCH * HW + p0 + nw * 32 + lc * 2;
            #pragma unroll
            for (int mt = 0; mt < 4; mt++) {
                float* orow = ob + (size_t)(mw * 64 + mt * 16 + lr) * HW;
                #pragma unroll
                for (int nt = 0; nt < 4; nt++) {
                    *(float2*)(orow + nt * 8)          = make_float2(acc[mt][nt][0], acc[mt][nt][1]);
                    *(float2*)(orow + 8 * HW + nt * 8) = make_float2(acc[mt][nt][2], acc[mt][nt][3]);
                }
            }
        }
    }
}

extern "C" void kernel_launch(void* const* d_in, const int* in_sizes, int n_in,
                              void* d_out, int out_size)
{
    const float* x = (const float*)d_in[0];   // (32,128,128,128) fp32
    const float* w = (const float*)d_in[1];   // (128,128) fp32
    float* out = (float*)d_out;

    cudaFuncSetAttribute(conv1x1_bf16_kernel,
                         cudaFuncAttributeMaxDynamicSharedMemorySize, SMEM_BYTES);
    conv1x1_bf16_kernel<<<GRID, NTHREADS, SMEM_BYTES>>>(x, w, out);
}

// round 14
// speedup vs baseline: 1.2156x; 1.2156x over previous
#include <cuda_runtime.h>
#include <cstdint>
#include <cstddef>

// 1x1 conv as GEMM on HMMA (mma.sync tf32), sm_103 target.
// out[b,o,p] = sum_i W[i,o] * x[b,i,p];  B=32, CIN=COUT=128, HW=16384.
// R14: fix compute/memory SERIALIZATION (dur ~= tensor 55us + DRAM 67us).
// Deep cp.async pipeline: 16-row B chunks (8KB), 5 rotating buffers,
// wait_group(3) -> 3-4 chunks (24-32KB) in flight per CTA during all of
// compute. A = W^T 64KB XOR-swizzled (R7 layout). smem 104KB -> 2 CTAs/SM.
// Tile M=128 x N=128 x K=128; 8 warps 2(M)x4(N), warp m64n32, tf32 HMMA.

#define HW      16384
#define NCH     128
#define TILE_N  128
#define NTILES  4096
#define GRID    304
#define NTHREADS 256

#define A_OFF   0                     // 128*128 floats, unpadded, swizzled
#define B_OFF   16384                 // 5 buffers x 2048 floats (16 rows x 128)
#define SMEM_FLOATS (16384 + 5 * 2048)
#define SMEM_BYTES  (SMEM_FLOATS * 4)     // 106496 B

__device__ __forceinline__ uint32_t smem_u32(const void* p) {
    uint32_t a;
    asm("{ .reg .u64 t; cvta.to.shared.u64 t, %1; cvt.u32.u64 %0, t; }" : "=r"(a) : "l"(p));
    return a;
}

#define CP_ASYNC16(smaddr, gptr) \
    asm volatile("cp.async.cg.shared.global [%0], [%1], 16;" \
        :: "r"(smaddr), "l"(__cvta_generic_to_global(gptr)) : "memory")
#define CP_COMMIT() asm volatile("cp.async.commit_group;" ::: "memory")
#define CP_WAIT3()  asm volatile("cp.async.wait_group 3;" ::: "memory")

__device__ __forceinline__ void mma_tf32(float c[4], uint32_t a0, uint32_t a1,
                                         uint32_t a2, uint32_t a3,
                                         uint32_t b0, uint32_t b1) {
    asm volatile(
        "mma.sync.aligned.m16n8k8.row.col.f32.tf32.tf32.f32 "
        "{%0,%1,%2,%3},{%4,%5,%6,%7},{%8,%9},{%0,%1,%2,%3};"
        : "+f"(c[0]), "+f"(c[1]), "+f"(c[2]), "+f"(c[3])
        : "r"(a0), "r"(a1), "r"(a2), "r"(a3), "r"(b0), "r"(b1));
}

__global__ __launch_bounds__(NTHREADS, 2)
void conv1x1_hmma_kernel(const float* __restrict__ x,
                         const float* __restrict__ w,
                         float* __restrict__ out)
{
    extern __shared__ __align__(16) float smem[];
    const uint32_t sb = smem_u32(smem);
    const int tid = threadIdx.x;
    const int lid = tid & 31;
    const int wid = tid >> 5;
    const int mw  = wid & 1;          // M half
    const int nw  = wid >> 1;         // N quarter
    const int bid = blockIdx.x;
    const int lr  = lid >> 2;         // 0..7
    const int lc  = lid & 3;          // 0..3

    // ---- W^T -> A smem once, RN-rounded tf32, XOR-swizzled (R7 layout):
    // word(o,k) = o*128 + ((k>>3)*8 ^ ((o&3)<<3)) + (k&3)*2 + ((k>>2)&1)
    for (int i = tid; i < NCH * NCH; i += NTHREADS) {
        int k = i >> 7, o = i & 127;
        float v = __ldg(&w[k * NCH + o]);
        uint32_t t;
        asm("cvt.rna.tf32.f32 %0, %1;" : "=r"(t) : "f"(v));
        int wd = o * 128 + (((k >> 3) * 8) ^ ((o & 3) << 3)) + (k & 3) * 2 + ((k >> 2) & 1);
        smem[A_OFF + wd] = __uint_as_float(t);
    }
    __syncthreads();

    const int n     = (NTILES - bid + GRID - 1) / GRID;
    const int total = 8 * n;            // 16-row chunks

    // ---- chunk loader: 16 k-rows x 128 px into buffer lb, col ^= (row&3)<<3
    auto load_chunk = [&](int g, int lb) {
        int t  = bid + (g >> 3) * GRID;
        int b  = t >> 7;
        int p0 = (t & 127) * TILE_N;
        int k0 = (g & 7) * 16;
        const float* xb = x + ((size_t)b * NCH + k0) * HW + p0;
        uint32_t base = sb + (uint32_t)(B_OFF + lb * 2048) * 4u;
        #pragma unroll
        for (int j = 0; j < 2; j++) {
            int id  = tid + j * NTHREADS;      // 0..511
            int row = id >> 5;                 // 0..15
            int px4 = (id & 31) * 4;
            uint32_t wd = (uint32_t)(row * 128 + (px4 ^ ((row & 3) << 3)));
            CP_ASYNC16(base + wd * 4u, xb + (size_t)row * HW + px4);
        }
    };

    load_chunk(0, 0); CP_COMMIT();
    if (total > 1) load_chunk(1, 1);
    CP_COMMIT();
    if (total > 2) load_chunk(2, 2);
    CP_COMMIT();
    if (total > 3) load_chunk(3, 3);
    CP_COMMIT();

    const int kxor = (lr & 3) << 3;
    const float* Asm = smem + A_OFF + (mw * 64 + lr) * 128 + lc * 2;
    float acc[4][4][4];

    int cb = 0, lb = 4;                 // compute / load buffer (mod 5)
    #pragma unroll 1
    for (int g = 0; g < total; g++) {
        CP_WAIT3();                     // group g done; g+1..g+3 stay in flight
        __syncthreads();                // all warps past compute(g-1)

        if (g + 4 < total) load_chunk(g + 4, lb);
        CP_COMMIT();                    // unconditional: group count stays exact
        lb = (lb == 4) ? 0 : lb + 1;

        if ((g & 7) == 0) {
            #pragma unroll
            for (int mt = 0; mt < 4; mt++)
                #pragma unroll
                for (int nt = 0; nt < 4; nt++)
                    #pragma unroll
                    for (int q = 0; q < 4; q++) acc[mt][nt][q] = 0.f;
        }

        const float* Bs = smem + B_OFF + cb * 2048 + nw * 32 + lr;
        cb = (cb == 4) ? 0 : cb + 1;
        const int kk0 = (g & 7) * 2;

        #pragma unroll
        for (int kl = 0; kl < 2; kl++) {
            const int kk = kk0 + kl;
            uint32_t af[4][4];
            #pragma unroll
            for (int mt = 0; mt < 4; mt++) {
                const float* pa = Asm + mt * 16 * 128 + ((kk * 8) ^ kxor);
                asm volatile("ld.shared.v2.b32 {%0,%1}, [%2];"
                    : "=r"(af[mt][0]), "=r"(af[mt][2]) : "r"(smem_u32(pa)));
                asm volatile("ld.shared.v2.b32 {%0,%1}, [%2];"
                    : "=r"(af[mt][1]), "=r"(af[mt][3]) : "r"(smem_u32(pa + 8 * 128)));
            }
            uint32_t bf[4][2];
            const float* pb = Bs + (kl * 8 + lc) * 128;
            #pragma unroll
            for (int nt = 0; nt < 4; nt++) {
                int sw = (nt ^ lc) * 8;
                bf[nt][0] = __float_as_uint(pb[sw]);
                bf[nt][1] = __float_as_uint(pb[4 * 128 + sw]);
            }
            #pragma unroll
            for (int mt = 0; mt < 4; mt++)
                #pragma unroll
                for (int nt = 0; nt < 4; nt++)
                    mma_tf32(acc[mt][nt], af[mt][0], af[mt][1], af[mt][2], af[mt][3],
                             bf[nt][0], bf[nt][1]);
        }

        if ((g & 7) == 7) {             // tile finished -> epilogue
            int t  = bid + (g >> 3) * GRID;
            int b  = t >> 7;
            int p0 = (t & 127) * TILE_N;
            float* ob = out + (size_t)b * NCH * HW + p0 + nw * 32 + lc * 2;
            #pragma unroll
            for (int mt = 0; mt < 4; mt++) {
                float* orow = ob + (size_t)(mw * 64 + mt * 16 + lr) * HW;
                #pragma unroll
                for (int nt = 0; nt < 4; nt++) {
                    *(float2*)(orow + nt * 8)          = make_float2(acc[mt][nt][0], acc[mt][nt][1]);
                    *(float2*)(orow + 8 * HW + nt * 8) = make_float2(acc[mt][nt][2], acc[mt][nt][3]);
                }
            }
        }
    }
}

extern "C" void kernel_launch(void* const* d_in, const int* in_sizes, int n_in,
                              void* d_out, int out_size)
{
    const float* x = (const float*)d_in[0];   // (32,128,128,128) fp32
    const float* w = (const float*)d_in[1];   // (128,128) fp32
    float* out = (float*)d_out;

    cudaFuncSetAttribute(conv1x1_hmma_kernel,
                         cudaFuncAttributeMaxDynamicSharedMemorySize, SMEM_BYTES);
    conv1x1_hmma_kernel<<<GRID, NTHREADS, SMEM_BYTES>>>(x, w, out);
}

// round 16
// speedup vs baseline: 1.2929x; 1.0635x over previous
#include <cuda_runtime.h>
#include <cuda.h>
#include <cstdint>
#include <cstddef>

// 1x1 conv as GEMM on HMMA (mma.sync tf32), sm_103 target.
// out[b,o,p] = sum_i W[i,o] * x[b,i,p];  B=32, CIN=COUT=128, HW=16384.
// R16: R15 (B staged via TMA cp.async.bulk.tensor.2d + mbarrier expect_tx)
// with the host typedef fixed (CUtensorMapFloatOOBfill). TMA removes ~1024
// LDGSTS per chunk from the warps' issue/LSU budget and the staging L1
// wavefronts. A = W^T 64KB XOR-swizzled (conflict-free). B chunks 32 rows x
// 128 px, 2 buffers, TMA SW128. Tile M=128 x N=128 x K=128; 8 warps
// 2(M)x4(N), warp m64n32. 2 CTAs/SM.

#define HW      16384
#define NCH     128
#define TILE_N  128
#define NTILES  4096
#define GRID    304
#define NTHREADS 256

#define A_OFF     0                   // 16384 words
#define B_OFF     16384               // 2 buffers x 4096 words (32r x 128px)
#define MBAR_WOFF 24576               // 2 mbarriers (16 bytes)
#define SMEM_WORDS (24576 + 8)
#define SMEM_BYTES (SMEM_WORDS * 4)   // 98336 B -> 2 CTAs/SM

__device__ __forceinline__ uint32_t smem_u32(const void* p) {
    uint32_t a;
    asm("{ .reg .u64 t; cvta.to.shared.u64 t, %1; cvt.u32.u64 %0, t; }" : "=r"(a) : "l"(p));
    return a;
}

#define MBARRIER_INIT(addr, cnt) \
    asm volatile("mbarrier.init.shared.b64 [%0], %1;" :: "r"(addr), "r"(cnt) : "memory")
#define MBARRIER_EXPECT_TX(addr, bytes) \
    asm volatile("mbarrier.arrive.expect_tx.shared.b64 _, [%0], %1;" \
        :: "r"(addr), "r"(bytes) : "memory")
#define MBAR_WAIT(addr, par) do {                                              \
    uint32_t _m = (addr); uint32_t _p = (par);                                 \
    asm volatile("{\n\t.reg .pred P1;\n\t"                                     \
        "W_%=: mbarrier.try_wait.parity.shared.b64 P1, [%0], %1;\n\t"          \
        "@P1 bra.uni D_%=;\n\t bra.uni W_%=;\n\tD_%=:\n\t}"                    \
        :: "r"(_m), "r"(_p) : "memory");                                       \
} while (0)

#define TMA_LOAD_2D(dst, tmap, cx, cy, mbar) \
    asm volatile("cp.async.bulk.tensor.2d.shared::cta.global.tile.mbarrier::complete_tx::bytes " \
        "[%0], [%1, {%2, %3}], [%4];" \
        :: "r"(dst), "l"(tmap), "r"(cx), "r"(cy), "r"(mbar) : "memory")

__device__ __forceinline__ void mma_tf32(float c[4], uint32_t a0, uint32_t a1,
                                         uint32_t a2, uint32_t a3,
                                         uint32_t b0, uint32_t b1) {
    asm volatile(
        "mma.sync.aligned.m16n8k8.row.col.f32.tf32.tf32.f32 "
        "{%0,%1,%2,%3},{%4,%5,%6,%7},{%8,%9},{%0,%1,%2,%3};"
        : "+f"(c[0]), "+f"(c[1]), "+f"(c[2]), "+f"(c[3])
        : "r"(a0), "r"(a1), "r"(a2), "r"(a3), "r"(b0), "r"(b1));
}

__global__ __launch_bounds__(NTHREADS, 2)
void conv1x1_tma_kernel(const float* __restrict__ w,
                        float* __restrict__ out,
                        const __grid_constant__ CUtensorMap tmap)
{
    extern __shared__ __align__(128) float smem[];
    const uint32_t sb = smem_u32(smem);
    const int tid = threadIdx.x;
    const int lid = tid & 31;
    const int wid = tid >> 5;
    const int mw  = wid & 1;          // M half
    const int nw  = wid >> 1;         // N quarter
    const int bid = blockIdx.x;
    const int lr  = lid >> 2;         // 0..7
    const int lc  = lid & 3;          // 0..3

    // ---- W^T -> A smem once, RN-rounded tf32, XOR-swizzled (R7 layout):
    // word(o,k) = o*128 + ((k>>3)*8 ^ ((o&3)<<3)) + (k&3)*2 + ((k>>2)&1)
    for (int i = tid; i < NCH * NCH; i += NTHREADS) {
        int k = i >> 7, o = i & 127;
        float v = __ldg(&w[k * NCH + o]);
        uint32_t t;
        asm("cvt.rna.tf32.f32 %0, %1;" : "=r"(t) : "f"(v));
        int wd = o * 128 + (((k >> 3) * 8) ^ ((o & 3) << 3)) + (k & 3) * 2 + ((k >> 2) & 1);
        smem[A_OFF + wd] = __uint_as_float(t);
    }
    const uint32_t mb = sb + MBAR_WOFF * 4u;
    if (tid == 0) {
        MBARRIER_INIT(mb, 1);
        MBARRIER_INIT(mb + 8, 1);
    }
    __syncthreads();

    const int n     = (NTILES - bid + GRID - 1) / GRID;
    const int total = 4 * n;            // 32-row chunks

    // ---- TMA chunk issue (thread 0 only): 4 boxes of 32px x 32 k-rows
    auto issue_chunk = [&](int g) {
        int t  = bid + (g >> 2) * GRID;
        int b  = t >> 7;
        int p0 = (t & 127) * TILE_N;
        int cy = b * NCH + (g & 3) * 32;           // global row (b*128 + k0)
        uint32_t s = g & 1;
        MBARRIER_EXPECT_TX(mb + s * 8, 16384u);
        uint32_t dst = sb + (uint32_t)(B_OFF + s * 4096) * 4u;
        #pragma unroll
        for (int r = 0; r < 4; r++)
            TMA_LOAD_2D(dst + r * 4096u, &tmap, p0 + r * 32, cy, mb + s * 8);
    };

    if (tid == 0) issue_chunk(0);

    const int kxor = (lr & 3) << 3;
    const float* Asm = smem + A_OFF + (mw * 64 + lr) * 128 + lc * 2;
    float acc[4][4][4];

    #pragma unroll 1
    for (int g = 0; g < total; g++) {
        // issue next chunk: its buffer was last computed on in iter g-1,
        // and the end-of-(g-1) __syncthreads guarantees all warps finished.
        if (tid == 0 && g + 1 < total) issue_chunk(g + 1);

        MBAR_WAIT(mb + (g & 1) * 8, (g >> 1) & 1);   // chunk g resident

        if ((g & 3) == 0) {
            #pragma unroll
            for (int mt = 0; mt < 4; mt++)
                #pragma unroll
                for (int nt = 0; nt < 4; nt++)
                    #pragma unroll
                    for (int q = 0; q < 4; q++) acc[mt][nt][q] = 0.f;
        }

        // B region for this warp: 32px column-group nw, TMA SW128 layout:
        // word(row, c) = row*32 + (c ^ ((row&7)<<2)),  c = lr + nt*8
        const float* Bs = smem + B_OFF + (g & 1) * 4096 + nw * 1024;
        const int kk0 = (g & 3) * 4;

        #pragma unroll
        for (int kl = 0; kl < 4; kl++) {
            const int kk = kk0 + kl;
            uint32_t af[4][4];
            #pragma unroll
            for (int mt = 0; mt < 4; mt++) {
                const float* pa = Asm + mt * 16 * 128 + ((kk * 8) ^ kxor);
                asm volatile("ld.shared.v2.b32 {%0,%1}, [%2];"
                    : "=r"(af[mt][0]), "=r"(af[mt][2]) : "r"(smem_u32(pa)));
                asm volatile("ld.shared.v2.b32 {%0,%1}, [%2];"
                    : "=r"(af[mt][1]), "=r"(af[mt][3]) : "r"(smem_u32(pa + 8 * 128)));
            }
            uint32_t bf[4][2];
            const int r0 = kl * 8 + lc;              // b0 row; b1 row = r0+4
            #pragma unroll
            for (int nt = 0; nt < 4; nt++) {
                int c = lr + nt * 8;
                bf[nt][0] = __float_as_uint(Bs[r0 * 32 + (c ^ (lc << 2))]);
                bf[nt][1] = __float_as_uint(Bs[(r0 + 4) * 32 + (c ^ (lc << 2) ^ 16)]);
            }
            #pragma unroll
            for (int mt = 0; mt < 4; mt++)
                #pragma unroll
                for (int nt = 0; nt < 4; nt++)
                    mma_tf32(acc[mt][nt], af[mt][0], af[mt][1], af[mt][2], af[mt][3],
                             bf[nt][0], bf[nt][1]);
        }

        if ((g & 3) == 3) {                          // tile finished -> epilogue
            int t  = bid + (g >> 2) * GRID;
            int b  = t >> 7;
            int p0 = (t & 127) * TILE_N;
            float* ob = out + (size_t)b * NCH * HW + p0 + nw * 32 + lc * 2;
            #pragma unroll
            for (int mt = 0; mt < 4; mt++) {
                float* orow = ob + (size_t)(mw * 64 + mt * 16 + lr) * HW;
                #pragma unroll
                for (int nt = 0; nt < 4; nt++) {
                    *(float2*)(orow + nt * 8)          = make_float2(acc[mt][nt][0], acc[mt][nt][1]);
                    *(float2*)(orow + 8 * HW + nt * 8) = make_float2(acc[mt][nt][2], acc[mt][nt][3]);
                }
            }
        }
        __syncthreads();    // all warps done with buf (g&1) -> safe to refill
    }
}

typedef CUresult (*PFN_tmapEncode)(
    CUtensorMap*, CUtensorMapDataType, cuuint32_t, void*,
    const cuuint64_t*, const cuuint64_t*, const cuuint32_t*, const cuuint32_t*,
    CUtensorMapInterleave, CUtensorMapSwizzle, CUtensorMapL2promotion,
    CUtensorMapFloatOOBfill);

extern "C" void kernel_launch(void* const* d_in, const int* in_sizes, int n_in,
                              void* d_out, int out_size)
{
    const float* x = (const float*)d_in[0];   // (32,128,128,128) fp32
    const float* w = (const float*)d_in[1];   // (128,128) fp32
    float* out = (float*)d_out;

    // Build TMA descriptor: x viewed as [4096 rows x 16384 px] fp32,
    // box = 32 px x 32 rows, SW128 swizzle.  (Driver entry point fetched via
    // the runtime so no -lcuda link is needed; recomputed every call.)
    PFN_tmapEncode encode = nullptr;
    cudaDriverEntryPointQueryResult qr;
    cudaGetDriverEntryPoint("cuTensorMapEncodeTiled", (void**)&encode,
                            cudaEnableDefault, &qr);
    CUtensorMap tmap;
    cuuint64_t gdim[2]    = { (cuuint64_t)HW, (cuuint64_t)(NCH * 32) };
    cuuint64_t gstride[1] = { (cuuint64_t)HW * 4 };
    cuuint32_t box[2]     = { 32, 32 };
    cuuint32_t estride[2] = { 1, 1 };
    encode(&tmap, CU_TENSOR_MAP_DATA_TYPE_FLOAT32, 2, (void*)x,
           gdim, gstride, box, estride,
           CU_TENSOR_MAP_INTERLEAVE_NONE, CU_TENSOR_MAP_SWIZZLE_128B,
           CU_TENSOR_MAP_L2_PROMOTION_L2_128B, CU_TENSOR_MAP_FLOAT_OOB_FILL_NONE);

    cudaFuncSetAttribute(conv1x1_tma_kernel,
                         cudaFuncAttributeMaxDynamicSharedMemorySize, SMEM_BYTES);
    conv1x1_tma_kernel<<<GRID, NTHREADS, SMEM_BYTES>>>(w, out, tmap);
}